// round 1
// baseline (speedup 1.0000x reference)
#include <cuda_runtime.h>

// ---------------- problem constants ----------------
#define NN 10000
#define LL 256
#define EE 160000
#define HH 64
#define DM 4
#define DS 32
#define DC 4
#define DI 8
#define NLAYERS 8
#define EPSV 1e-6f

// ---------------- scratch (device globals; no allocation) ----------------
__device__ float g_h[NN * HH];          // node features
__device__ float g_e[EE * HH];          // edge features (updated in place)
__device__ float g_hw[NN * 5 * HH];     // A1|A2|A3|B1|B2 per node
__device__ float g_aggf[NN * HH];
__device__ float g_aggb[NN * HH];
__device__ float g_x2[NN * DM];
__device__ int g_deg_in[NN], g_deg_out[NN];
__device__ int g_ofs_in[NN + 1], g_ofs_out[NN + 1];
__device__ int g_cur_in[NN], g_cur_out[NN];
__device__ int g_csr_in[EE], g_csr_out[EE];

__device__ __forceinline__ float sigmoidf_(float x) {
    return 1.f / (1.f + __expf(-x));
}

// ---------------- CSR build ----------------
__global__ void k_zero_deg() {
    int i = blockIdx.x * blockDim.x + threadIdx.x;
    if (i < NN) { g_deg_in[i] = 0; g_deg_out[i] = 0; }
}

__global__ void k_hist(const int* __restrict__ src, const int* __restrict__ dst) {
    int i = blockIdx.x * blockDim.x + threadIdx.x;
    if (i < EE) {
        atomicAdd(&g_deg_in[dst[i]], 1);
        atomicAdd(&g_deg_out[src[i]], 1);
    }
}

__global__ void k_scan() {
    __shared__ int part[1024];
    int t = threadIdx.x;
    for (int pass = 0; pass < 2; pass++) {
        const int* deg = pass ? g_deg_out : g_deg_in;
        int* ofs = pass ? g_ofs_out : g_ofs_in;
        int* cur = pass ? g_cur_out : g_cur_in;
        int lo = t * 10;
        int hi = lo + 10; if (hi > NN) hi = NN;
        int s = 0;
        for (int i = lo; i < hi && i < NN; i++) s += deg[i];
        part[t] = s;
        __syncthreads();
        for (int d = 1; d < 1024; d <<= 1) {
            int add = (t >= d) ? part[t - d] : 0;
            __syncthreads();
            part[t] += add;
            __syncthreads();
        }
        int run = part[t] - s;  // exclusive base
        for (int i = lo; i < hi && i < NN; i++) {
            ofs[i] = run; cur[i] = run; run += deg[i];
        }
        if (lo < NN && hi == NN) ofs[NN] = run;
        __syncthreads();
    }
}

__global__ void k_fill(const int* __restrict__ src, const int* __restrict__ dst) {
    int i = blockIdx.x * blockDim.x + threadIdx.x;
    if (i < EE) {
        int p = atomicAdd(&g_cur_in[dst[i]], 1);
        g_csr_in[p] = i;
        int q = atomicAdd(&g_cur_out[src[i]], 1);
        g_csr_out[q] = i;
    }
}

// deterministic summation order: sort edge ids within each node segment
__global__ void k_sortcsr() {
    int n = blockIdx.x * blockDim.x + threadIdx.x;
    if (n >= 2 * NN) return;
    int* csr; int beg, end;
    if (n < NN) { csr = g_csr_in;  beg = g_ofs_in[n];        end = g_ofs_in[n + 1]; }
    else        { csr = g_csr_out; beg = g_ofs_out[n - NN];  end = g_ofs_out[n - NN + 1]; }
    for (int i = beg + 1; i < end; i++) {
        int key = csr[i]; int j = i - 1;
        while (j >= beg && csr[j] > key) { csr[j + 1] = csr[j]; j--; }
        csr[j + 1] = key;
    }
}

// ---------------- encoders: out = relu(in@W1 + b1)@W2 + b2  (Fin=2, I=16, H=64) ----------------
__global__ void k_enc(const float* __restrict__ in, const float* __restrict__ W1,
                      const float* __restrict__ b1, const float* __restrict__ W2,
                      const float* __restrict__ b2, int rows, int target_e) {
    float* outp = target_e ? g_e : g_h;
    int tid = threadIdx.x;
    int j = tid & 63, g = tid >> 6;  // 4 rows per block-iter
    float w1a[16], w1b[16], bb1[16], w2c[16];
#pragma unroll
    for (int i = 0; i < 16; i++) {
        w1a[i] = W1[i];
        w1b[i] = W1[16 + i];
        bb1[i] = b1[i];
        w2c[i] = W2[i * 64 + j];
    }
    float b2j = b2[j];
    for (int r = blockIdx.x * 4 + g; r < rows; r += gridDim.x * 4) {
        float x0 = in[r * 2], x1 = in[r * 2 + 1];
        float acc = b2j;
#pragma unroll
        for (int i = 0; i < 16; i++) {
            float hid = fmaxf(x0 * w1a[i] + x1 * w1b[i] + bb1[i], 0.f);
            acc += hid * w2c[i];
        }
        outp[r * 64 + j] = acc;
    }
}

// ---------------- per-layer node GEMM: g_hw = h @ [W0..W4] + b ----------------
__global__ void k_hw(const float* __restrict__ gnn_W, const float* __restrict__ gnn_b, int l) {
    __shared__ float hs[4][64];
    int tid = threadIdx.x;       // 320 threads
    int m = tid >> 6, j = tid & 63;
    const float* Wm = gnn_W + (size_t)(l * 6 + m) * 4096;
    float w[64];
#pragma unroll
    for (int k = 0; k < 64; k++) w[k] = Wm[k * 64 + j];
    float bias = gnn_b[(l * 6 + m) * 64 + j];
    for (int nb = blockIdx.x * 4; nb < NN; nb += gridDim.x * 4) {
        __syncthreads();
        if (tid < 256) {
            int nn = nb + (tid >> 6);
            hs[tid >> 6][tid & 63] = (nn < NN) ? g_h[nn * 64 + (tid & 63)] : 0.f;
        }
        __syncthreads();
#pragma unroll
        for (int b = 0; b < 4; b++) {
            int nn = nb + b;
            if (nn >= NN) break;
            float acc = bias;
            const float4* h4 = (const float4*)hs[b];
#pragma unroll
            for (int k4 = 0; k4 < 16; k4++) {
                float4 v = h4[k4];
                acc += v.x * w[4 * k4] + v.y * w[4 * k4 + 1] + v.z * w[4 * k4 + 2] + v.w * w[4 * k4 + 3];
            }
            g_hw[(size_t)nn * 320 + m * 64 + j] = acc;
        }
    }
}

// ---------------- per-layer edge update: e += relu(B1h[src]+B2h[dst] + e@W5 + b5) ----------------
__global__ void k_edge(const int* __restrict__ src, const int* __restrict__ dst,
                       const float* __restrict__ gnn_W, const float* __restrict__ gnn_b, int l) {
    __shared__ float es[4][64];
    int tid = threadIdx.x;
    int g = tid >> 6, j = tid & 63;
    const float* W5 = gnn_W + (size_t)(l * 6 + 5) * 4096;
    float w[64];
#pragma unroll
    for (int k = 0; k < 64; k++) w[k] = W5[k * 64 + j];
    float b5 = gnn_b[(l * 6 + 5) * 64 + j];
    for (int base = blockIdx.x * 4; base < EE; base += gridDim.x * 4) {
        int eg = base + g;
        __syncthreads();
        es[g][j] = (eg < EE) ? g_e[(size_t)eg * 64 + j] : 0.f;
        __syncthreads();
        if (eg < EE) {
            float acc = b5;
            const float4* e4 = (const float4*)es[g];
#pragma unroll
            for (int k4 = 0; k4 < 16; k4++) {
                float4 v = e4[k4];
                acc += v.x * w[4 * k4] + v.y * w[4 * k4 + 1] + v.z * w[4 * k4 + 2] + v.w * w[4 * k4 + 3];
            }
            int s = src[eg], d = dst[eg];
            acc += g_hw[(size_t)s * 320 + 192 + j] + g_hw[(size_t)d * 320 + 256 + j];
            g_e[(size_t)eg * 64 + j] = es[g][j] + fmaxf(acc, 0.f);
        }
    }
}

// ---------------- per-layer aggregation via CSR gather ----------------
__global__ void k_agg(const int* __restrict__ src, const int* __restrict__ dst) {
    int b = blockIdx.x;
    int j = threadIdx.x;  // 64
    bool fwd = b < NN;
    int n = fwd ? b : b - NN;
    const int* ofs = fwd ? g_ofs_in : g_ofs_out;
    const int* csr = fwd ? g_csr_in : g_csr_out;
    const int* oth = fwd ? src : dst;
    int off = fwd ? 64 : 128;  // A2h for forward, A3h for backward
    int beg = ofs[n], end = ofs[n + 1];
    float num = 0.f, den = 0.f;
    for (int p = beg; p < end; p++) {
        int ed = csr[p];
        float v = g_e[(size_t)ed * 64 + j];
        float sg = sigmoidf_(v);
        int o = oth[ed];
        num += sg * g_hw[(size_t)o * 320 + off + j];
        den += sg;
    }
    float* outp = fwd ? g_aggf : g_aggb;
    outp[n * 64 + j] = num / (den + EPSV);
}

__global__ void k_hupd() {
    int idx = blockIdx.x * blockDim.x + threadIdx.x;
    if (idx < NN * 64) {
        int n = idx >> 6, j = idx & 63;
        float v = g_hw[(size_t)n * 320 + j] + g_aggf[idx] + g_aggb[idx];
        g_h[idx] += fmaxf(v, 0.f);
    }
}

// ---------------- mamba: warp per node, lane = state index s; scan stops at rl-1 ----------------
__global__ void k_mamba(const float* __restrict__ reads, const int* __restrict__ read_length,
                        const float* __restrict__ in_proj_W, const float* __restrict__ conv_W,
                        const float* __restrict__ conv_b, const float* __restrict__ x_proj_W,
                        const float* __restrict__ dt_proj_W, const float* __restrict__ dt_proj_b,
                        const float* __restrict__ A_log, const float* __restrict__ Dskip,
                        const float* __restrict__ out_proj_W) {
    __shared__ float ip[64], cw[32], cb[8], xp[8 * 65], dtw[8], dtb[8], As[256], Dsk[8], op[32];
    __shared__ float ys[8][8], os[8][8];
    int tid = threadIdx.x;
    if (tid < 64) ip[tid] = in_proj_W[tid];
    if (tid < 32) { cw[tid] = conv_W[tid]; op[tid] = out_proj_W[tid]; }
    if (tid < 8) {
        cb[tid] = conv_b[tid]; dtw[tid] = dt_proj_W[tid];
        dtb[tid] = dt_proj_b[tid]; Dsk[tid] = Dskip[tid];
    }
    for (int i = tid; i < 520; i += blockDim.x) xp[i] = x_proj_W[i];
    for (int i = tid; i < 256; i += blockDim.x) As[i] = -__expf(A_log[i]) * 1.44269504f;
    __syncthreads();
    int warp = tid >> 5, lane = tid & 31;
    int n = blockIdx.x * 8 + warp;
    if (n >= NN) return;
    int rl = read_length[n];
    float hst[8];
#pragma unroll
    for (int i = 0; i < 8; i++) hst[i] = 0.f;
    float x0 = 0.f, x1 = 0.f, x2v = 0.f;
    float xc = 0.f, zf = 0.f, CsLast = 0.f;
    const float4* rd4 = (const float4*)(reads + (size_t)n * LL * 4);
    int li = lane & 7;
    for (int t = 0; t < rl; t++) {
        float4 rd = rd4[t];
        float xcv = 0.f;
        if (lane < 8) {
            float xh = rd.x * ip[lane] + rd.y * ip[16 + lane] + rd.z * ip[32 + lane] + rd.w * ip[48 + lane];
            float c = x0 * cw[lane * 4] + x1 * cw[lane * 4 + 1] + x2v * cw[lane * 4 + 2] + xh * cw[lane * 4 + 3] + cb[lane];
            x0 = x1; x1 = x2v; x2v = xh;
            xcv = c * sigmoidf_(c);  // silu
            if (t == rl - 1)
                zf = rd.x * ip[8 + lane] + rd.y * ip[24 + lane] + rd.z * ip[40 + lane] + rd.w * ip[56 + lane];
        }
        xc = xcv;
        float dbl0 = 0.f, Bs = 0.f, Cs = 0.f;
#pragma unroll
        for (int i = 0; i < 8; i++) {
            float xi = __shfl_sync(0xffffffffu, xc, i);
            dbl0 += xi * xp[i * 65];
            Bs += xi * xp[i * 65 + 1 + lane];
            Cs += xi * xp[i * 65 + 33 + lane];
        }
        float dr = dbl0 * dtw[li] + dtb[li];
        float dtv = (dr > 15.f) ? dr : __logf(1.f + __expf(dr));
#pragma unroll
        for (int i = 0; i < 8; i++) {
            float dti = __shfl_sync(0xffffffffu, dtv, i);
            float xi = __shfl_sync(0xffffffffu, xc, i);
            hst[i] = exp2f(dti * As[i * 32 + lane]) * hst[i] + (dti * Bs) * xi;
        }
        if (t == rl - 1) CsLast = Cs;
    }
#pragma unroll
    for (int i = 0; i < 8; i++) {
        float v = hst[i] * CsLast;
#pragma unroll
        for (int off = 16; off; off >>= 1) v += __shfl_xor_sync(0xffffffffu, v, off);
        if (lane == 0) ys[warp][i] = v;
    }
    __syncwarp();
    if (lane < 8) {
        float y = ys[warp][lane] + xc * Dsk[lane];
        os[warp][lane] = y * (zf * sigmoidf_(zf));
    }
    __syncwarp();
    if (lane < 4) {
        float acc = 0.f;
#pragma unroll
        for (int i = 0; i < 8; i++) acc += os[warp][i] * op[i * 4 + lane];
        g_x2[n * 4 + lane] = acc;
    }
}

// ---------------- h += x2 @ base_W + base_b ----------------
__global__ void k_base(const float* __restrict__ base_W, const float* __restrict__ base_b) {
    int idx = blockIdx.x * blockDim.x + threadIdx.x;
    if (idx < NN * 64) {
        int n = idx >> 6, j = idx & 63;
        float v = g_x2[n * 4 + 0] * base_W[j] + g_x2[n * 4 + 1] * base_W[64 + j]
                + g_x2[n * 4 + 2] * base_W[128 + j] + g_x2[n * 4 + 3] * base_W[192 + j] + base_b[j];
        g_h[idx] += v;
    }
}

// ---------------- prediction head: relu([h[src],h[dst],e] @ Wp1 + bp1) @ Wp2 + bp2 ----------------
__global__ void k_pred(const int* __restrict__ src, const int* __restrict__ dst,
                       const float* __restrict__ Wp1, const float* __restrict__ bp1,
                       const float* __restrict__ Wp2, const float* __restrict__ bp2,
                       float* __restrict__ out) {
    __shared__ float cs[16][192];
    __shared__ int ssrc[16], sdst[16];
    __shared__ float wp2s[64], bp1s[64];
    int tid = threadIdx.x;
    if (tid < 64) { wp2s[tid] = Wp2[tid]; bp1s[tid] = bp1[tid]; }
    int t16 = tid & 15, g = tid >> 4;
    float bp2v = bp2[0];
    for (int base = blockIdx.x * 16; base < EE; base += gridDim.x * 16) {
        __syncthreads();
        if (tid < 16) {
            int e2 = base + tid;
            ssrc[tid] = (e2 < EE) ? src[e2] : 0;
            sdst[tid] = (e2 < EE) ? dst[e2] : 0;
        }
        __syncthreads();
        for (int idx = tid; idx < 16 * 192; idx += 256) {
            int ge = idx / 192, k = idx - ge * 192;
            int e2 = base + ge;
            float v = 0.f;
            if (e2 < EE) {
                if (k < 64) v = g_h[(size_t)ssrc[ge] * 64 + k];
                else if (k < 128) v = g_h[(size_t)sdst[ge] * 64 + (k - 64)];
                else v = g_e[(size_t)e2 * 64 + (k - 128)];
            }
            cs[ge][k] = v;
        }
        __syncthreads();
        int e2 = base + g;
        float a0 = bp1s[t16 * 4], a1 = bp1s[t16 * 4 + 1], a2 = bp1s[t16 * 4 + 2], a3 = bp1s[t16 * 4 + 3];
        const float4* c4 = (const float4*)cs[g];
        const float4* wbase = (const float4*)Wp1;
#pragma unroll 4
        for (int k4 = 0; k4 < 48; k4++) {
            float4 cv = c4[k4];
            const float4* wp = wbase + (k4 * 4) * 16 + t16;
            float4 w0 = __ldg(wp);
            float4 w1 = __ldg(wp + 16);
            float4 w2 = __ldg(wp + 32);
            float4 w3 = __ldg(wp + 48);
            a0 += cv.x * w0.x + cv.y * w1.x + cv.z * w2.x + cv.w * w3.x;
            a1 += cv.x * w0.y + cv.y * w1.y + cv.z * w2.y + cv.w * w3.y;
            a2 += cv.x * w0.z + cv.y * w1.z + cv.z * w2.z + cv.w * w3.z;
            a3 += cv.x * w0.w + cv.y * w1.w + cv.z * w2.w + cv.w * w3.w;
        }
        float p = fmaxf(a0, 0.f) * wp2s[t16 * 4] + fmaxf(a1, 0.f) * wp2s[t16 * 4 + 1]
                + fmaxf(a2, 0.f) * wp2s[t16 * 4 + 2] + fmaxf(a3, 0.f) * wp2s[t16 * 4 + 3];
#pragma unroll
        for (int off = 8; off; off >>= 1) p += __shfl_down_sync(0xffffffffu, p, off, 16);
        if (t16 == 0 && e2 < EE) out[e2] = p + bp2v;
    }
}

// ---------------- launch ----------------
extern "C" void kernel_launch(void* const* d_in, const int* in_sizes, int n_in,
                              void* d_out, int out_size) {
    const float* x        = (const float*)d_in[0];
    const float* e_in     = (const float*)d_in[1];
    const float* reads    = (const float*)d_in[2];
    const int*   src      = (const int*)d_in[3];
    const int*   dst      = (const int*)d_in[4];
    const int*   rl       = (const int*)d_in[5];
    const float* W1n      = (const float*)d_in[6];
    const float* b1n      = (const float*)d_in[7];
    const float* W2n      = (const float*)d_in[8];
    const float* b2n      = (const float*)d_in[9];
    const float* W1e      = (const float*)d_in[10];
    const float* b1e      = (const float*)d_in[11];
    const float* W2e      = (const float*)d_in[12];
    const float* b2e      = (const float*)d_in[13];
    const float* gnn_W    = (const float*)d_in[14];
    const float* gnn_b    = (const float*)d_in[15];
    const float* in_projW = (const float*)d_in[16];
    const float* conv_W   = (const float*)d_in[17];
    const float* conv_b   = (const float*)d_in[18];
    const float* x_projW  = (const float*)d_in[19];
    const float* dt_projW = (const float*)d_in[20];
    const float* dt_projb = (const float*)d_in[21];
    const float* A_log    = (const float*)d_in[22];
    const float* Dskip    = (const float*)d_in[23];
    const float* out_projW= (const float*)d_in[24];
    const float* base_W   = (const float*)d_in[25];
    const float* base_b   = (const float*)d_in[26];
    const float* Wp1      = (const float*)d_in[27];
    const float* bp1      = (const float*)d_in[28];
    const float* Wp2      = (const float*)d_in[29];
    const float* bp2      = (const float*)d_in[30];
    float* out = (float*)d_out;

    // CSR build (recomputed every call; deterministic after sort)
    k_zero_deg<<<(NN + 255) / 256, 256>>>();
    k_hist<<<(EE + 255) / 256, 256>>>(src, dst);
    k_scan<<<1, 1024>>>();
    k_fill<<<(EE + 255) / 256, 256>>>(src, dst);
    k_sortcsr<<<(2 * NN + 255) / 256, 256>>>();

    // encoders
    k_enc<<<512, 256>>>(x, W1n, b1n, W2n, b2n, NN, 0);
    k_enc<<<2048, 256>>>(e_in, W1e, b1e, W2e, b2e, EE, 1);

    // mamba (independent of GNN state)
    k_mamba<<<1250, 256>>>(reads, rl, in_projW, conv_W, conv_b, x_projW,
                           dt_projW, dt_projb, A_log, Dskip, out_projW);

    // GNN layers
    for (int l = 0; l < NLAYERS; l++) {
        k_hw<<<256, 320>>>(gnn_W, gnn_b, l);
        k_edge<<<2048, 256>>>(src, dst, gnn_W, gnn_b, l);
        k_agg<<<2 * NN, 64>>>(src, dst);
        k_hupd<<<(NN * 64 + 255) / 256, 256>>>();
    }

    // base add + prediction
    k_base<<<(NN * 64 + 255) / 256, 256>>>(base_W, base_b);
    k_pred<<<1024, 256>>>(src, dst, Wp1, bp1, Wp2, bp2, out);
}